// round 7
// baseline (speedup 1.0000x reference)
#include <cuda_runtime.h>
#include <cuda_bf16.h>
#include <cstdint>

// ---------------------------------------------------------------------------
// HME: out[b,o] = sum_{i,l} pw[o,i,l] * lp[b,l] * x_leaf[b,i] + sum_l lp[b,l]*pb[o,l]
// Rewritten as NT GEMM: A[1024,32768] @ pw[512,32768]^T with A[b, i*64+l] =
// x_leaf[b,i]*lp[b,l] generated on the fly (lp part cached in registers).
// tf32 mma.sync, split-K=4 with deterministic scratch reduction.
// ---------------------------------------------------------------------------

#define B_SZ 1024
#define OF 512
#define IF 512
#define GF 512
#define NLEAF 64
#define NGATE 63

#define BM 128
#define BN 128
#define SK 4
#define STEPS 128            // i-steps per CTA (512 / SK)
#define BSTRIDE 68           // padded B-tile row stride (floats): banks 4g+t4 distinct
#define XSTRIDE 132          // padded X-tile row stride (floats)
#define NSTAGE 3
#define SMEM_FLOATS (NSTAGE*128*BSTRIDE + 128*XSTRIDE)
#define SMEM_BYTES (SMEM_FLOATS * 4)

__device__ float g_lp[B_SZ * NLEAF];                    // leaf probs
__device__ float g_scratch[(size_t)SK * B_SZ * OF];     // split-K partials (8 MB)

// ---------------------------------------------------------------------------
// Kernel 1: gatings = sigmoid(x_gating @ gw + gb); tree-product -> lp[1024,64]
// ---------------------------------------------------------------------------
__global__ __launch_bounds__(256) void k_gating(const float* __restrict__ xg,
                                                const float* __restrict__ gw,
                                                const float* __restrict__ gb) {
    __shared__ float gs[8 * NGATE];
    const int t = threadIdx.x;
    const int b0 = blockIdx.x * 8;

    #pragma unroll
    for (int q = 0; q < 2; q++) {
        int task = t + q * 256;
        if (task < 8 * NGATE) {
            int gi = task % NGATE;
            int lb = task / NGATE;
            const float* xr = xg + (size_t)(b0 + lb) * GF;
            float acc = gb[gi];
            #pragma unroll 8
            for (int f = 0; f < GF; f++)
                acc += xr[f] * gw[(size_t)f * NGATE + gi];
            gs[lb * NGATE + gi] = 1.0f / (1.0f + expf(-acc));
        }
    }
    __syncthreads();

    #pragma unroll
    for (int q = 0; q < 2; q++) {
        int task = t + q * 256;          // 512 tasks = 8 batches * 64 leaves
        int lb = task >> 6;
        int l  = task & 63;
        float p = 1.0f;
        #pragma unroll
        for (int d = 0; d < 6; d++) {
            int pidx = l >> (6 - d);
            int idx  = (1 << d) - 1 + pidx;
            float g  = gs[lb * NGATE + idx];
            int s    = (l >> (5 - d)) & 1;
            p *= s ? (1.0f - g) : g;
        }
        g_lp[(size_t)(b0 + lb) * NLEAF + l] = p;
    }
}

// ---------------------------------------------------------------------------
// tf32 helpers
// ---------------------------------------------------------------------------
__device__ __forceinline__ uint32_t f2tf32(float x) {
    uint32_t u;
    asm("cvt.rna.tf32.f32 %0, %1;" : "=r"(u) : "f"(x));
    return u;
}

__device__ __forceinline__ void mma_tf32(float acc[4], const uint32_t a[4],
                                         uint32_t b0, uint32_t b1) {
    asm volatile(
        "mma.sync.aligned.m16n8k8.row.col.f32.tf32.tf32.f32 "
        "{%0,%1,%2,%3}, {%4,%5,%6,%7}, {%8,%9}, {%0,%1,%2,%3};\n"
        : "+f"(acc[0]), "+f"(acc[1]), "+f"(acc[2]), "+f"(acc[3])
        : "r"(a[0]), "r"(a[1]), "r"(a[2]), "r"(a[3]), "r"(b0), "r"(b1));
}

// One K-step (k=64): A fragment = xv ⊗ lp (lp held in regs), B from smem tile.
__device__ __forceinline__ void mma_step(const float xv[2][2],
                                         const float* __restrict__ Bbuf,
                                         const float lpf[2][2][16],
                                         float acc[2][8][4],
                                         int wn, int g8, int t4) {
    #pragma unroll
    for (int kf = 0; kf < 8; kf++) {
        uint32_t a[2][4];
        #pragma unroll
        for (int mi = 0; mi < 2; mi++) {
            a[mi][0] = f2tf32(xv[mi][0] * lpf[mi][0][kf * 2 + 0]);
            a[mi][1] = f2tf32(xv[mi][1] * lpf[mi][1][kf * 2 + 0]);
            a[mi][2] = f2tf32(xv[mi][0] * lpf[mi][0][kf * 2 + 1]);
            a[mi][3] = f2tf32(xv[mi][1] * lpf[mi][1][kf * 2 + 1]);
        }
        #pragma unroll
        for (int nt = 0; nt < 8; nt++) {
            const float* bp = Bbuf + (wn * 64 + nt * 8 + g8) * BSTRIDE + kf * 8 + t4;
            uint32_t b0 = __float_as_uint(bp[0]);
            uint32_t b1 = __float_as_uint(bp[4]);
            #pragma unroll
            for (int mi = 0; mi < 2; mi++)
                mma_tf32(acc[mi][nt], a[mi], b0, b1);
        }
    }
}

// B-tile async loader: step s -> pw[:, i_global*64 .. +64). Always commits a
// group (possibly empty) so wait_group counts stay consistent.
__device__ __forceinline__ void issue_load(int s, int t, int sk,
                                           const float* __restrict__ pwbase,
                                           float* __restrict__ Bs) {
    if (s < STEPS) {
        int ig = sk * STEPS + s;
        float* dst = Bs + (s % NSTAGE) * 128 * BSTRIDE;
        const float* src = pwbase + (size_t)ig * 64;
        #pragma unroll
        for (int q = 0; q < 8; q++) {
            int id  = t + q * 256;
            int row = id >> 4;
            int cv  = id & 15;
            uint32_t sa = (uint32_t)__cvta_generic_to_shared(dst + row * BSTRIDE + cv * 4);
            const float* ga = src + (size_t)row * 32768 + cv * 4;
            asm volatile("cp.async.cg.shared.global [%0], [%1], 16;\n"
                         :: "r"(sa), "l"(ga));
        }
    }
    asm volatile("cp.async.commit_group;\n");
}

// ---------------------------------------------------------------------------
// Kernel 2: split-K GEMM. grid (4 nb, 8 mb, 4 sk), 256 threads.
// ---------------------------------------------------------------------------
__global__ __launch_bounds__(256, 1) void k_gemm(const float* __restrict__ xl,
                                                 const float* __restrict__ pw,
                                                 const float* __restrict__ pb) {
    extern __shared__ float sm[];
    float* Bs = sm;                                 // NSTAGE * 128 * BSTRIDE
    float* Xs = sm + NSTAGE * 128 * BSTRIDE;        // 128 * XSTRIDE

    const int t    = threadIdx.x;
    const int lane = t & 31;
    const int w    = t >> 5;
    const int g8   = lane >> 2;
    const int t4   = lane & 3;
    const int wm   = w & 3;      // 0..3 -> m offset wm*32
    const int wn   = w >> 2;     // 0..1 -> n offset wn*64
    const int nb = blockIdx.x, mb = blockIdx.y, sk = blockIdx.z;

    // --- load X tile [128 rows][128 i-cols] (coalesced, padded stride) ---
    {
        const float* xbase = xl + (size_t)(mb * 128) * IF + sk * STEPS;
        #pragma unroll
        for (int q = 0; q < 16; q++) {
            int id  = t + q * 256;
            int row = id >> 5;
            int c4  = id & 31;
            float4 v = *(const float4*)(xbase + (size_t)row * IF + c4 * 4);
            *(float4*)(Xs + row * XSTRIDE + c4 * 4) = v;
        }
    }

    // --- load lp fragments into registers (constant over the whole K-loop) ---
    float lpf[2][2][16];
    #pragma unroll
    for (int mi = 0; mi < 2; mi++)
        #pragma unroll
        for (int r01 = 0; r01 < 2; r01++) {
            int rloc = wm * 32 + mi * 16 + r01 * 8 + g8;
            const float* lprow = g_lp + (size_t)(mb * 128 + rloc) * NLEAF;
            #pragma unroll
            for (int kf = 0; kf < 8; kf++) {
                lpf[mi][r01][kf * 2 + 0] = lprow[kf * 8 + t4];
                lpf[mi][r01][kf * 2 + 1] = lprow[kf * 8 + t4 + 4];
            }
        }

    float acc[2][8][4];
    #pragma unroll
    for (int mi = 0; mi < 2; mi++)
        #pragma unroll
        for (int nt = 0; nt < 8; nt++)
            #pragma unroll
            for (int c = 0; c < 4; c++)
                acc[mi][nt][c] = 0.0f;

    const float* pwbase = pw + (size_t)(nb * 128) * 32768;

    issue_load(0, t, sk, pwbase, Bs);
    issue_load(1, t, sk, pwbase, Bs);

    for (int s = 0; s < STEPS; s++) {
        issue_load(s + 2, t, sk, pwbase, Bs);
        asm volatile("cp.async.wait_group 2;\n");
        __syncthreads();

        const float* Bbuf = Bs + (s % NSTAGE) * 128 * BSTRIDE;
        float xv[2][2];
        #pragma unroll
        for (int mi = 0; mi < 2; mi++)
            #pragma unroll
            for (int r01 = 0; r01 < 2; r01++)
                xv[mi][r01] = Xs[(wm * 32 + mi * 16 + r01 * 8 + g8) * XSTRIDE + s];

        mma_step(xv, Bbuf, lpf, acc, wn, g8, t4);
        __syncthreads();
    }

    // --- bias step (only last K-slice): A = lp (x==1), B = pb[128 rows][64] ---
    if (sk == SK - 1) {
        asm volatile("cp.async.wait_group 0;\n");
        __syncthreads();
        #pragma unroll
        for (int q = 0; q < 8; q++) {
            int id  = t + q * 256;
            int row = id >> 4;
            int cv  = id & 15;
            float4 v = *(const float4*)(pb + (size_t)(nb * 128 + row) * NLEAF + cv * 4);
            *(float4*)(Bs + row * BSTRIDE + cv * 4) = v;
        }
        __syncthreads();
        float xv1[2][2] = {{1.0f, 1.0f}, {1.0f, 1.0f}};
        mma_step(xv1, Bs, lpf, acc, wn, g8, t4);
    }

    // --- store partials ---
    float* sc = g_scratch + (size_t)sk * B_SZ * OF;
    #pragma unroll
    for (int mi = 0; mi < 2; mi++)
        #pragma unroll
        for (int nt = 0; nt < 8; nt++) {
            int r0  = mb * 128 + wm * 32 + mi * 16 + g8;
            int col = nb * 128 + wn * 64 + nt * 8 + t4 * 2;
            *(float2*)(sc + (size_t)r0 * OF + col) =
                make_float2(acc[mi][nt][0], acc[mi][nt][1]);
            *(float2*)(sc + (size_t)(r0 + 8) * OF + col) =
                make_float2(acc[mi][nt][2], acc[mi][nt][3]);
        }
}

// ---------------------------------------------------------------------------
// Kernel 3: deterministic split-K reduction
// ---------------------------------------------------------------------------
__global__ __launch_bounds__(256) void k_reduce(float* __restrict__ out) {
    const int i = blockIdx.x * 256 + threadIdx.x;   // float4 index, 131072 total
    const float4* s = (const float4*)g_scratch;
    float4 a = s[i];
    float4 b = s[i + 131072];
    float4 c = s[i + 262144];
    float4 d = s[i + 393216];
    float4 r;
    r.x = (a.x + b.x) + (c.x + d.x);
    r.y = (a.y + b.y) + (c.y + d.y);
    r.z = (a.z + b.z) + (c.z + d.z);
    r.w = (a.w + b.w) + (c.w + d.w);
    ((float4*)out)[i] = r;
}

// ---------------------------------------------------------------------------
extern "C" void kernel_launch(void* const* d_in, const int* in_sizes, int n_in,
                              void* d_out, int out_size) {
    const float* xg = (const float*)d_in[0];   // [1024, 512]
    const float* xl = (const float*)d_in[1];   // [1024, 512]
    const float* gw = (const float*)d_in[2];   // [512, 63]
    const float* gb = (const float*)d_in[3];   // [63]
    const float* pw = (const float*)d_in[4];   // [512, 512, 64]
    const float* pb = (const float*)d_in[5];   // [512, 64]
    float* out = (float*)d_out;                // [1024, 512]

    cudaFuncSetAttribute(k_gemm, cudaFuncAttributeMaxDynamicSharedMemorySize,
                         SMEM_BYTES);

    k_gating<<<B_SZ / 8, 256>>>(xg, gw, gb);
    k_gemm<<<dim3(OF / BN, B_SZ / BM, SK), 256, SMEM_BYTES>>>(xl, pw, pb);
    k_reduce<<<(B_SZ * OF / 4) / 256, 256>>>(out);
}

// round 9
// speedup vs baseline: 1.7335x; 1.7335x over previous
#include <cuda_runtime.h>
#include <cuda_bf16.h>
#include <cstdint>

// ---------------------------------------------------------------------------
// HME: out[b,o] = sum_{i,l} pw[o,i,l] * lp[b,l] * x_leaf[b,i] + lp@pb^T
// NT GEMM A[1024,32768] @ pw[512,32768]^T, A[b,i*64+l] = x_leaf[b,i]*lp[b,l]
// built on the fly (lp cached in registers). tf32 mma.sync (sm_103 has no
// tcgen05 in this harness -- ptxas targets sm_103, not sm_103a).
// Split-K=4 with deterministic scratch reduction.
// ---------------------------------------------------------------------------

#define B_SZ 1024
#define OF 512
#define IF 512
#define GF 512
#define NLEAF 64
#define NGATE 63

#define BM 128
#define BN 128
#define SK 4
#define STEPS 128            // i-steps per CTA (512 / SK)
#define BSTRIDE 68           // padded B-tile row stride (floats)
#define XSTRIDE 132          // padded X-tile row stride (floats)
#define NSTAGE 3
#define SMEM_FLOATS (NSTAGE*128*BSTRIDE + 128*XSTRIDE)
#define SMEM_BYTES (SMEM_FLOATS * 4)

__device__ float g_lp[B_SZ * NLEAF];                    // leaf probs
__device__ float g_gwT[NGATE * GF];                     // transposed gate weights
__device__ float g_scratch[(size_t)SK * B_SZ * OF];     // split-K partials

// ---------------------------------------------------------------------------
// Kernel 0: transpose gw[512][63] -> gwT[63][512]
// ---------------------------------------------------------------------------
__global__ __launch_bounds__(256) void k_transpose(const float* __restrict__ gw) {
    int idx = blockIdx.x * 256 + threadIdx.x;
    if (idx < GF * NGATE) {
        int f = idx / NGATE;
        int g = idx % NGATE;
        g_gwT[g * GF + f] = gw[idx];
    }
}

// ---------------------------------------------------------------------------
// Kernel 1: gating GEMV + sigmoid + tree-product -> g_lp[1024][64]
// 256 blocks x 256 threads, 4 batches/block, warp handles 8 gates.
// ---------------------------------------------------------------------------
__global__ __launch_bounds__(256) void k_gating(const float* __restrict__ xg,
                                                const float* __restrict__ gb) {
    __shared__ float gsh[4][64];
    const int t = threadIdx.x;
    const int lane = t & 31;
    const int w = t >> 5;
    const int b0 = blockIdx.x * 4;

    #pragma unroll
    for (int j = 0; j < 8; j++) {
        int g = w * 8 + j;
        if (g < NGATE) {
            float wrow[16];
            #pragma unroll
            for (int q = 0; q < 16; q++)
                wrow[q] = g_gwT[(size_t)g * GF + lane + 32 * q];
            #pragma unroll
            for (int bb = 0; bb < 4; bb++) {
                const float* xr = xg + (size_t)(b0 + bb) * GF;
                float acc = 0.0f;
                #pragma unroll
                for (int q = 0; q < 16; q++)
                    acc += wrow[q] * xr[lane + 32 * q];
                #pragma unroll
                for (int o = 16; o > 0; o >>= 1)
                    acc += __shfl_xor_sync(0xFFFFFFFFu, acc, o);
                if (lane == 0)
                    gsh[bb][g] = 1.0f / (1.0f + expf(-(acc + gb[g])));
            }
        }
    }
    __syncthreads();

    {
        int bb = t >> 6;
        int l = t & 63;
        float p = 1.0f;
        #pragma unroll
        for (int d = 0; d < 6; d++) {
            int idx = (1 << d) - 1 + (l >> (6 - d));
            float g = gsh[bb][idx];
            p *= ((l >> (5 - d)) & 1) ? (1.0f - g) : g;
        }
        g_lp[(size_t)(b0 + bb) * NLEAF + l] = p;
    }
}

// --------------------------------------------------------------------------
// Dummy no-op kernel (profiling alignment: puts k_gemm at global launch #5)
// --------------------------------------------------------------------------
__global__ void k_nop() {}

// ---------------------------------------------------------------------------
// tf32 helpers
// ---------------------------------------------------------------------------
__device__ __forceinline__ uint32_t f2tf32(float x) {
    uint32_t u;
    asm("cvt.rna.tf32.f32 %0, %1;" : "=r"(u) : "f"(x));
    return u;
}

__device__ __forceinline__ void mma_tf32(float acc[4], const uint32_t a[4],
                                         uint32_t b0, uint32_t b1) {
    asm volatile(
        "mma.sync.aligned.m16n8k8.row.col.f32.tf32.tf32.f32 "
        "{%0,%1,%2,%3}, {%4,%5,%6,%7}, {%8,%9}, {%0,%1,%2,%3};\n"
        : "+f"(acc[0]), "+f"(acc[1]), "+f"(acc[2]), "+f"(acc[3])
        : "r"(a[0]), "r"(a[1]), "r"(a[2]), "r"(a[3]), "r"(b0), "r"(b1));
}

// One K-step (k=64): A fragment = xv ⊗ lp (lp held in regs), B from smem tile.
__device__ __forceinline__ void mma_step(const float xv[2][2],
                                         const float* __restrict__ Bbuf,
                                         const float lpf[2][2][16],
                                         float acc[2][8][4],
                                         int wn, int g8, int t4) {
    #pragma unroll
    for (int kf = 0; kf < 8; kf++) {
        uint32_t a[2][4];
        #pragma unroll
        for (int mi = 0; mi < 2; mi++) {
            a[mi][0] = f2tf32(xv[mi][0] * lpf[mi][0][kf * 2 + 0]);
            a[mi][1] = f2tf32(xv[mi][1] * lpf[mi][1][kf * 2 + 0]);
            a[mi][2] = f2tf32(xv[mi][0] * lpf[mi][0][kf * 2 + 1]);
            a[mi][3] = f2tf32(xv[mi][1] * lpf[mi][1][kf * 2 + 1]);
        }
        #pragma unroll
        for (int nt = 0; nt < 8; nt++) {
            const float* bp = Bbuf + (wn * 64 + nt * 8 + g8) * BSTRIDE + kf * 8 + t4;
            uint32_t b0 = __float_as_uint(bp[0]);
            uint32_t b1 = __float_as_uint(bp[4]);
            #pragma unroll
            for (int mi = 0; mi < 2; mi++)
                mma_tf32(acc[mi][nt], a[mi], b0, b1);
        }
    }
}

// B-tile async loader: step s -> pw[:, i_global*64 .. +64). Always commits a
// group (possibly empty) so wait_group counts stay consistent.
__device__ __forceinline__ void issue_load(int s, int t, int sk,
                                           const float* __restrict__ pwbase,
                                           float* __restrict__ Bs) {
    if (s < STEPS) {
        int ig = sk * STEPS + s;
        float* dst = Bs + (s % NSTAGE) * 128 * BSTRIDE;
        const float* src = pwbase + (size_t)ig * 64;
        #pragma unroll
        for (int q = 0; q < 8; q++) {
            int id  = t + q * 256;
            int row = id >> 4;
            int cv  = id & 15;
            uint32_t sa = (uint32_t)__cvta_generic_to_shared(dst + row * BSTRIDE + cv * 4);
            const float* ga = src + (size_t)row * 32768 + cv * 4;
            asm volatile("cp.async.cg.shared.global [%0], [%1], 16;\n"
                         :: "r"(sa), "l"(ga));
        }
    }
    asm volatile("cp.async.commit_group;\n");
}

// ---------------------------------------------------------------------------
// Kernel 2: split-K GEMM. grid (4 nb, 8 mb, 4 sk), 256 threads.
// Single barrier per K-step: [wait_group 1; bar; issue(s+2); mma(s)].
// issue(s+2) writes stage (s+2)%3 == (s-1)%3 whose readers are all pre-bar.
// ---------------------------------------------------------------------------
__global__ __launch_bounds__(256, 1) void k_gemm(const float* __restrict__ xl,
                                                 const float* __restrict__ pw,
                                                 const float* __restrict__ pb) {
    extern __shared__ float sm[];
    float* Bs = sm;                                 // NSTAGE * 128 * BSTRIDE
    float* Xs = sm + NSTAGE * 128 * BSTRIDE;        // 128 * XSTRIDE

    const int t    = threadIdx.x;
    const int lane = t & 31;
    const int w    = t >> 5;
    const int g8   = lane >> 2;
    const int t4   = lane & 3;
    const int wm   = w & 3;      // 0..3 -> m offset wm*32
    const int wn   = w >> 2;     // 0..1 -> n offset wn*64
    const int nb = blockIdx.x, mb = blockIdx.y, sk = blockIdx.z;

    // --- load X tile [128 rows][128 i-cols] (coalesced, padded stride) ---
    {
        const float* xbase = xl + (size_t)(mb * 128) * IF + sk * STEPS;
        #pragma unroll
        for (int q = 0; q < 16; q++) {
            int id  = t + q * 256;
            int row = id >> 5;
            int c4  = id & 31;
            float4 v = *(const float4*)(xbase + (size_t)row * IF + c4 * 4);
            *(float4*)(Xs + row * XSTRIDE + c4 * 4) = v;
        }
    }

    // --- load lp fragments into registers (constant over the whole K-loop) ---
    float lpf[2][2][16];
    #pragma unroll
    for (int mi = 0; mi < 2; mi++)
        #pragma unroll
        for (int r01 = 0; r01 < 2; r01++) {
            int rloc = wm * 32 + mi * 16 + r01 * 8 + g8;
            const float* lprow = g_lp + (size_t)(mb * 128 + rloc) * NLEAF;
            #pragma unroll
            for (int kf = 0; kf < 8; kf++) {
                lpf[mi][r01][kf * 2 + 0] = lprow[kf * 8 + t4];
                lpf[mi][r01][kf * 2 + 1] = lprow[kf * 8 + t4 + 4];
            }
        }

    float acc[2][8][4];
    #pragma unroll
    for (int mi = 0; mi < 2; mi++)
        #pragma unroll
        for (int nt = 0; nt < 8; nt++)
            #pragma unroll
            for (int c = 0; c < 4; c++)
                acc[mi][nt][c] = 0.0f;

    const float* pwbase = pw + (size_t)(nb * 128) * 32768;

    issue_load(0, t, sk, pwbase, Bs);
    issue_load(1, t, sk, pwbase, Bs);

    for (int s = 0; s < STEPS; s++) {
        asm volatile("cp.async.wait_group 1;\n");   // stage s resident
        __syncthreads();                            // visible to all; s-1 reads done
        issue_load(s + 2, t, sk, pwbase, Bs);       // writes stage (s-1)%3: safe

        const float* Bbuf = Bs + (s % NSTAGE) * 128 * BSTRIDE;
        float xv[2][2];
        #pragma unroll
        for (int mi = 0; mi < 2; mi++)
            #pragma unroll
            for (int r01 = 0; r01 < 2; r01++)
                xv[mi][r01] = Xs[(wm * 32 + mi * 16 + r01 * 8 + g8) * XSTRIDE + s];

        mma_step(xv, Bbuf, lpf, acc, wn, g8, t4);
    }

    // --- bias step (only last K-slice): A = lp (x==1), B = pb[128 rows][64] ---
    if (sk == SK - 1) {
        asm volatile("cp.async.wait_group 0;\n");
        __syncthreads();
        #pragma unroll
        for (int q = 0; q < 8; q++) {
            int id  = t + q * 256;
            int row = id >> 4;
            int cv  = id & 15;
            float4 v = *(const float4*)(pb + (size_t)(nb * 128 + row) * NLEAF + cv * 4);
            *(float4*)(Bs + row * BSTRIDE + cv * 4) = v;
        }
        __syncthreads();
        float xv1[2][2] = {{1.0f, 1.0f}, {1.0f, 1.0f}};
        mma_step(xv1, Bs, lpf, acc, wn, g8, t4);
    }

    // --- store partials ---
    float* sc = g_scratch + (size_t)sk * B_SZ * OF;
    #pragma unroll
    for (int mi = 0; mi < 2; mi++)
        #pragma unroll
        for (int nt = 0; nt < 8; nt++) {
            int r0  = mb * 128 + wm * 32 + mi * 16 + g8;
            int col = nb * 128 + wn * 64 + nt * 8 + t4 * 2;
            *(float2*)(sc + (size_t)r0 * OF + col) =
                make_float2(acc[mi][nt][0], acc[mi][nt][1]);
            *(float2*)(sc + (size_t)(r0 + 8) * OF + col) =
                make_float2(acc[mi][nt][2], acc[mi][nt][3]);
        }
}

// ---------------------------------------------------------------------------
// Kernel 3: deterministic split-K reduction
// ---------------------------------------------------------------------------
__global__ __launch_bounds__(256) void k_reduce(float* __restrict__ out) {
    const int i = blockIdx.x * 256 + threadIdx.x;   // float4 index, 131072 total
    const float4* s = (const float4*)g_scratch;
    float4 a = s[i];
    float4 b = s[i + 131072];
    float4 c = s[i + 262144];
    float4 d = s[i + 393216];
    float4 r;
    r.x = (a.x + b.x) + (c.x + d.x);
    r.y = (a.y + b.y) + (c.y + d.y);
    r.z = (a.z + b.z) + (c.z + d.z);
    r.w = (a.w + b.w) + (c.w + d.w);
    ((float4*)out)[i] = r;
}

// ---------------------------------------------------------------------------
extern "C" void kernel_launch(void* const* d_in, const int* in_sizes, int n_in,
                              void* d_out, int out_size) {
    const float* xg = (const float*)d_in[0];   // [1024, 512]
    const float* xl = (const float*)d_in[1];   // [1024, 512]
    const float* gw = (const float*)d_in[2];   // [512, 63]
    const float* gb = (const float*)d_in[3];   // [63]
    const float* pw = (const float*)d_in[4];   // [512, 512, 64]
    const float* pb = (const float*)d_in[5];   // [512, 64]
    float* out = (float*)d_out;                // [1024, 512]

    cudaFuncSetAttribute(k_gemm, cudaFuncAttributeMaxDynamicSharedMemorySize,
                         SMEM_BYTES);

    k_transpose<<<(GF * NGATE + 255) / 256, 256>>>(gw);
    k_gating<<<B_SZ / 4, 256>>>(xg, gb);
    k_nop<<<1, 32>>>();          // launch #2 \
    k_nop<<<1, 32>>>();          // launch #3  > align ncu -s 5 onto k_gemm
    k_nop<<<1, 32>>>();          // launch #4 /
    k_gemm<<<dim3(OF / BN, B_SZ / BM, SK), 256, SMEM_BYTES>>>(xl, pw, pb);
    k_reduce<<<(B_SZ * OF / 4) / 256, 256>>>(out);
}

// round 10
// speedup vs baseline: 2.6639x; 1.5367x over previous
#include <cuda_runtime.h>
#include <cuda_fp16.h>
#include <cstdint>

// ---------------------------------------------------------------------------
// HME: out = einsum('oil,bl,bi->bo') + lp@pb^T  as one NT GEMM
// A[1024,32768] @ pwh[512,32768]^T,  A[b,i*64+l] = x_leaf[b,i]*lp[b,l].
// fp16 mma.sync m16n8k16 (same 11-bit mantissa as tf32, 2x the rate).
// pw converted to fp16 once per call (k_prep). Split-K=4 + reduction.
// ---------------------------------------------------------------------------

#define B_SZ 1024
#define OF 512
#define IF 512
#define GF 512
#define NLEAF 64
#define NGATE 63

#define SK 4
#define STEPS 128            // i-steps per CTA (512/SK)
#define SH 72                // B-stage row stride in halves (bank-conflict-free)
#define XSTRIDE 132
#define NSTAGE 3
#define BS_BYTES (NSTAGE * 128 * SH * 2)          // 55296
#define SMEM_BYTES (BS_BYTES + 128 * XSTRIDE * 4) // 122880

__device__ float  g_lp[B_SZ * NLEAF];
__device__ float  g_gwT[NGATE * GF];
__device__ __half g_pwh[(size_t)OF * IF * NLEAF];   // 33.5 MB fp16 pw
__device__ __half g_pbh[OF * NLEAF];
__device__ float  g_scratch[(size_t)SK * B_SZ * OF];

// ---------------------------------------------------------------------------
// Kernel 0: prep — gw transpose + pw/pb fp16 conversion
// ---------------------------------------------------------------------------
__global__ __launch_bounds__(256) void k_prep(const float* __restrict__ gw,
                                              const float* __restrict__ pw,
                                              const float* __restrict__ pb) {
    int idx = blockIdx.x * 256 + threadIdx.x;     // 0 .. 2097151
    // pw: 8 elements per thread
    {
        const float4* s = (const float4*)pw;
        float4 v0 = s[2 * idx];
        float4 v1 = s[2 * idx + 1];
        __half2 h0 = __floats2half2_rn(v0.x, v0.y);
        __half2 h1 = __floats2half2_rn(v0.z, v0.w);
        __half2 h2 = __floats2half2_rn(v1.x, v1.y);
        __half2 h3 = __floats2half2_rn(v1.z, v1.w);
        uint4 o;
        o.x = *(uint32_t*)&h0; o.y = *(uint32_t*)&h1;
        o.z = *(uint32_t*)&h2; o.w = *(uint32_t*)&h3;
        ((uint4*)g_pwh)[idx] = o;
    }
    // gw transpose
    if (idx < GF * NGATE) {
        int f = idx / NGATE;
        int g = idx % NGATE;
        g_gwT[g * GF + f] = gw[idx];
    }
    // pb convert: 32768 halves = 4096 threads x 8
    if (idx < (OF * NLEAF) / 8) {
        const float4* s = (const float4*)pb;
        float4 v0 = s[2 * idx];
        float4 v1 = s[2 * idx + 1];
        __half2 h0 = __floats2half2_rn(v0.x, v0.y);
        __half2 h1 = __floats2half2_rn(v0.z, v0.w);
        __half2 h2 = __floats2half2_rn(v1.x, v1.y);
        __half2 h3 = __floats2half2_rn(v1.z, v1.w);
        uint4 o;
        o.x = *(uint32_t*)&h0; o.y = *(uint32_t*)&h1;
        o.z = *(uint32_t*)&h2; o.w = *(uint32_t*)&h3;
        ((uint4*)g_pbh)[idx] = o;
    }
}

// ---------------------------------------------------------------------------
// Kernel 1: gating GEMV + sigmoid + tree-product -> g_lp[1024][64]
// ---------------------------------------------------------------------------
__global__ __launch_bounds__(256) void k_gating(const float* __restrict__ xg,
                                                const float* __restrict__ gb) {
    __shared__ float gsh[4][64];
    const int t = threadIdx.x;
    const int lane = t & 31;
    const int w = t >> 5;
    const int b0 = blockIdx.x * 4;

    #pragma unroll
    for (int j = 0; j < 8; j++) {
        int g = w * 8 + j;
        if (g < NGATE) {
            float wrow[16];
            #pragma unroll
            for (int q = 0; q < 16; q++)
                wrow[q] = g_gwT[(size_t)g * GF + lane + 32 * q];
            #pragma unroll
            for (int bb = 0; bb < 4; bb++) {
                const float* xr = xg + (size_t)(b0 + bb) * GF;
                float acc = 0.0f;
                #pragma unroll
                for (int q = 0; q < 16; q++)
                    acc += wrow[q] * xr[lane + 32 * q];
                #pragma unroll
                for (int o = 16; o > 0; o >>= 1)
                    acc += __shfl_xor_sync(0xFFFFFFFFu, acc, o);
                if (lane == 0)
                    gsh[bb][g] = 1.0f / (1.0f + expf(-(acc + gb[g])));
            }
        }
    }
    __syncthreads();

    {
        int bb = t >> 6;
        int l = t & 63;
        float p = 1.0f;
        #pragma unroll
        for (int d = 0; d < 6; d++) {
            int idx = (1 << d) - 1 + (l >> (6 - d));
            float g = gsh[bb][idx];
            p *= ((l >> (5 - d)) & 1) ? (1.0f - g) : g;
        }
        g_lp[(size_t)(b0 + bb) * NLEAF + l] = p;
    }
}

__global__ void k_nop() {}

// ---------------------------------------------------------------------------
// fp16 helpers
// ---------------------------------------------------------------------------
__device__ __forceinline__ uint32_t pack_h2(float lo, float hi) {
    uint32_t d;
    asm("cvt.rn.f16x2.f32 %0, %1, %2;" : "=r"(d) : "f"(hi), "f"(lo));
    return d;
}

__device__ __forceinline__ void mma_f16(float acc[4], const uint32_t a[4],
                                        uint32_t b0, uint32_t b1) {
    asm volatile(
        "mma.sync.aligned.m16n8k16.row.col.f32.f16.f16.f32 "
        "{%0,%1,%2,%3}, {%4,%5,%6,%7}, {%8,%9}, {%0,%1,%2,%3};\n"
        : "+f"(acc[0]), "+f"(acc[1]), "+f"(acc[2]), "+f"(acc[3])
        : "r"(a[0]), "r"(a[1]), "r"(a[2]), "r"(a[3]), "r"(b0), "r"(b1));
}

// One K-step (k=64): A = xv ⊗ lp packed to fp16, B from fp16 smem tile.
// lpf[mi][r01][kc*4+j]: lp at l = 16*kc + 2*t4 + (j&1) + ((j>>1)<<3)
__device__ __forceinline__ void mma_step(const float xv[2][2],
                                         const __half* __restrict__ Bh,
                                         const float lpf[2][2][16],
                                         float acc[2][8][4],
                                         int wn, int g8, int t4) {
    #pragma unroll
    for (int kc = 0; kc < 4; kc++) {
        uint32_t a[2][4];
        #pragma unroll
        for (int mi = 0; mi < 2; mi++) {
            a[mi][0] = pack_h2(xv[mi][0] * lpf[mi][0][kc * 4 + 0],
                               xv[mi][0] * lpf[mi][0][kc * 4 + 1]);
            a[mi][1] = pack_h2(xv[mi][1] * lpf[mi][1][kc * 4 + 0],
                               xv[mi][1] * lpf[mi][1][kc * 4 + 1]);
            a[mi][2] = pack_h2(xv[mi][0] * lpf[mi][0][kc * 4 + 2],
                               xv[mi][0] * lpf[mi][0][kc * 4 + 3]);
            a[mi][3] = pack_h2(xv[mi][1] * lpf[mi][1][kc * 4 + 2],
                               xv[mi][1] * lpf[mi][1][kc * 4 + 3]);
        }
        #pragma unroll
        for (int nt = 0; nt < 8; nt++) {
            const uint32_t* bp = (const uint32_t*)(Bh
                + (wn * 64 + nt * 8 + g8) * SH + kc * 16 + 2 * t4);
            uint32_t b0 = bp[0];
            uint32_t b1 = bp[4];   // k += 8 halves
            #pragma unroll
            for (int mi = 0; mi < 2; mi++)
                mma_f16(acc[mi][nt], a[mi], b0, b1);
        }
    }
}

// B-stage loader (fp16): 16 KB per stage, 4 x 16B chunks per thread.
__device__ __forceinline__ void issue_load(int s, int t, int sk,
                                           const __half* __restrict__ pwh_b,
                                           __half* __restrict__ Bsh) {
    if (s < STEPS) {
        int ig = sk * STEPS + s;
        __half* dst = Bsh + (s % NSTAGE) * 128 * SH;
        const __half* src = pwh_b + (size_t)ig * 64;
        #pragma unroll
        for (int q = 0; q < 4; q++) {
            int c = t + q * 256;          // 0..1023
            int r = c >> 3;               // row 0..127
            int cc = c & 7;               // 16B chunk (8 halves)
            uint32_t sa = (uint32_t)__cvta_generic_to_shared(dst + r * SH + cc * 8);
            const __half* ga = src + (size_t)r * 32768 + cc * 8;
            asm volatile("cp.async.cg.shared.global [%0], [%1], 16;\n"
                         :: "r"(sa), "l"(ga));
        }
    }
    asm volatile("cp.async.commit_group;\n");
}

// ---------------------------------------------------------------------------
// Kernel 2: split-K fp16 GEMM. grid (4 nb, 8 mb, 4 sk), 256 threads.
// ---------------------------------------------------------------------------
__global__ __launch_bounds__(256, 1) void k_gemm(const float* __restrict__ xl) {
    extern __shared__ __align__(16) char sm[];
    __half* Bs = (__half*)sm;                       // NSTAGE stages
    float* Xs = (float*)(sm + BS_BYTES);            // 128 x XSTRIDE

    const int t    = threadIdx.x;
    const int lane = t & 31;
    const int w    = t >> 5;
    const int g8   = lane >> 2;
    const int t4   = lane & 3;
    const int wm   = w & 3;
    const int wn   = w >> 2;
    const int nb = blockIdx.x, mb = blockIdx.y, sk = blockIdx.z;

    // --- X tile [128 rows][128 i-cols] ---
    {
        const float* xbase = xl + (size_t)(mb * 128) * IF + sk * STEPS;
        #pragma unroll
        for (int q = 0; q < 16; q++) {
            int id  = t + q * 256;
            int row = id >> 5;
            int c4  = id & 31;
            float4 v = *(const float4*)(xbase + (size_t)row * IF + c4 * 4);
            *(float4*)(Xs + row * XSTRIDE + c4 * 4) = v;
        }
    }

    // --- lp fragments (constant over K-loop) ---
    float lpf[2][2][16];
    #pragma unroll
    for (int mi = 0; mi < 2; mi++)
        #pragma unroll
        for (int r01 = 0; r01 < 2; r01++) {
            int rloc = wm * 32 + mi * 16 + r01 * 8 + g8;
            const float* lprow = g_lp + (size_t)(mb * 128 + rloc) * NLEAF;
            #pragma unroll
            for (int kc = 0; kc < 4; kc++)
                #pragma unroll
                for (int j = 0; j < 4; j++)
                    lpf[mi][r01][kc * 4 + j] =
                        lprow[kc * 16 + 2 * t4 + (j & 1) + ((j >> 1) << 3)];
        }

    float acc[2][8][4];
    #pragma unroll
    for (int mi = 0; mi < 2; mi++)
        #pragma unroll
        for (int nt = 0; nt < 8; nt++)
            #pragma unroll
            for (int c = 0; c < 4; c++)
                acc[mi][nt][c] = 0.0f;

    const __half* pwh_b = g_pwh + (size_t)(nb * 128) * 32768;

    issue_load(0, t, sk, pwh_b, Bs);
    issue_load(1, t, sk, pwh_b, Bs);

    for (int s = 0; s < STEPS; s++) {
        asm volatile("cp.async.wait_group 1;\n");
        __syncthreads();
        issue_load(s + 2, t, sk, pwh_b, Bs);    // writes stage (s-1)%3: safe

        const __half* Bbuf = Bs + (s % NSTAGE) * 128 * SH;
        float xv[2][2];
        #pragma unroll
        for (int mi = 0; mi < 2; mi++)
            #pragma unroll
            for (int r01 = 0; r01 < 2; r01++)
                xv[mi][r01] = Xs[(wm * 32 + mi * 16 + r01 * 8 + g8) * XSTRIDE + s];

        mma_step(xv, Bbuf, lpf, acc, wn, g8, t4);
    }

    // --- bias step (last K-slice only): A = lp, B = pbh tile ---
    if (sk == SK - 1) {
        asm volatile("cp.async.wait_group 0;\n");
        __syncthreads();
        #pragma unroll
        for (int q = 0; q < 4; q++) {
            int c = t + q * 256;
            int r = c >> 3;
            int cc = c & 7;
            uint32_t sa = (uint32_t)__cvta_generic_to_shared(Bs + r * SH + cc * 8);
            const __half* ga = g_pbh + (size_t)(nb * 128 + r) * 64 + cc * 8;
            asm volatile("cp.async.cg.shared.global [%0], [%1], 16;\n"
                         :: "r"(sa), "l"(ga));
        }
        asm volatile("cp.async.commit_group;\n");
        asm volatile("cp.async.wait_group 0;\n");
        __syncthreads();
        float xv1[2][2] = {{1.0f, 1.0f}, {1.0f, 1.0f}};
        mma_step(xv1, Bs, lpf, acc, wn, g8, t4);
    }

    // --- store partials ---
    float* sc = g_scratch + (size_t)sk * B_SZ * OF;
    #pragma unroll
    for (int mi = 0; mi < 2; mi++)
        #pragma unroll
        for (int nt = 0; nt < 8; nt++) {
            int r0  = mb * 128 + wm * 32 + mi * 16 + g8;
            int col = nb * 128 + wn * 64 + nt * 8 + t4 * 2;
            *(float2*)(sc + (size_t)r0 * OF + col) =
                make_float2(acc[mi][nt][0], acc[mi][nt][1]);
            *(float2*)(sc + (size_t)(r0 + 8) * OF + col) =
                make_float2(acc[mi][nt][2], acc[mi][nt][3]);
        }
}

// ---------------------------------------------------------------------------
// Kernel 3: deterministic split-K reduction
// ---------------------------------------------------------------------------
__global__ __launch_bounds__(256) void k_reduce(float* __restrict__ out) {
    const int i = blockIdx.x * 256 + threadIdx.x;
    const float4* s = (const float4*)g_scratch;
    float4 a = s[i];
    float4 b = s[i + 131072];
    float4 c = s[i + 262144];
    float4 d = s[i + 393216];
    float4 r;
    r.x = (a.x + b.x) + (c.x + d.x);
    r.y = (a.y + b.y) + (c.y + d.y);
    r.z = (a.z + b.z) + (c.z + d.z);
    r.w = (a.w + b.w) + (c.w + d.w);
    ((float4*)out)[i] = r;
}

// ---------------------------------------------------------------------------
extern "C" void kernel_launch(void* const* d_in, const int* in_sizes, int n_in,
                              void* d_out, int out_size) {
    const float* xg = (const float*)d_in[0];   // [1024, 512]
    const float* xl = (const float*)d_in[1];   // [1024, 512]
    const float* gw = (const float*)d_in[2];   // [512, 63]
    const float* gb = (const float*)d_in[3];   // [63]
    const float* pw = (const float*)d_in[4];   // [512, 512, 64]
    const float* pb = (const float*)d_in[5];   // [512, 64]
    float* out = (float*)d_out;                // [1024, 512]

    cudaFuncSetAttribute(k_gemm, cudaFuncAttributeMaxDynamicSharedMemorySize,
                         SMEM_BYTES);

    k_prep<<<8192, 256>>>(gw, pw, pb);                       // launch 0
    k_gating<<<B_SZ / 4, 256>>>(xg, gb);                     // launch 1
    k_gemm<<<dim3(4, 8, SK), 256, SMEM_BYTES>>>(xl);         // launch 2
    k_reduce<<<(B_SZ * OF / 4) / 256, 256>>>(out);           // launch 3
    k_nop<<<1, 32>>>();   // pad cycle to 7 so ncu probe (idx 9)
    k_nop<<<1, 32>>>();   // = cycle-2 position 2 = k_gemm
    k_nop<<<1, 32>>>();
}